// round 1
// baseline (speedup 1.0000x reference)
#include <cuda_runtime.h>
#include <cstdint>

#define EPS 1e-7f

// Global accumulators (no device allocation allowed).
__device__ double g_mse_sum;
__device__ double g_iou_sum;
__device__ unsigned long long g_n_inc;
__device__ unsigned long long g_n_corr;

__global__ void init_kernel() {
    g_mse_sum = 0.0;
    g_iou_sum = 0.0;
    g_n_inc = 0ull;
    g_n_corr = 0ull;
}

__global__ void __launch_bounds__(256) iou_reduce_kernel(
    const float4* __restrict__ pr,
    const float4* __restrict__ gt,
    int n)
{
    float mse_sum = 0.f;
    float iou_sum = 0.f;
    unsigned int n_inc = 0;
    unsigned int n_corr = 0;

    int stride = gridDim.x * blockDim.x;
    for (int i = blockIdx.x * blockDim.x + threadIdx.x; i < n; i += stride) {
        float4 p = __ldg(&pr[i]);
        float4 g = __ldg(&gt[i]);

        // gt corners
        float x_min_t = g.x - g.z * 0.5f;
        float x_max_t = g.x + g.z * 0.5f;
        float y_min_t = g.y - g.w * 0.5f;
        float y_max_t = g.y + g.w * 0.5f;
        // pred corners, clipped to [0,1]
        float x_min_p = fmaxf(p.x - p.z * 0.5f, 0.0f);
        float x_max_p = fminf(p.x + p.z * 0.5f, 1.0f);
        float y_min_p = fmaxf(p.y - p.w * 0.5f, 0.0f);
        float y_max_p = fminf(p.y + p.w * 0.5f, 1.0f);
        // overlap box
        float o0 = fmaxf(x_min_t, x_min_p);
        float o1 = fmaxf(y_min_t, y_min_p);
        float o2 = fminf(x_max_t, x_max_p);
        float o3 = fminf(y_max_t, y_max_p);

        bool incorrect = (o2 < o0) || (o3 < o1);
        if (incorrect) {
            float dx = p.x - g.x, dy = p.y - g.y, dz = p.z - g.z, dw = p.w - g.w;
            mse_sum += dx * dx + dy * dy + dz * dz + dw * dw;
            n_inc++;
        } else {
            float area_p = p.z * p.w;
            float area_g = g.z * g.w;
            float inter = (o2 - o0) * (o3 - o1);
            float iou = inter / (area_p + area_g - inter + EPS);
            iou_sum += iou;
            n_corr++;
        }
    }

    // Warp reduce
    #pragma unroll
    for (int off = 16; off > 0; off >>= 1) {
        mse_sum += __shfl_down_sync(0xffffffffu, mse_sum, off);
        iou_sum += __shfl_down_sync(0xffffffffu, iou_sum, off);
        n_inc   += __shfl_down_sync(0xffffffffu, n_inc, off);
        n_corr  += __shfl_down_sync(0xffffffffu, n_corr, off);
    }

    __shared__ float s_mse[8], s_iou[8];
    __shared__ unsigned int s_inc[8], s_corr[8];
    int lane = threadIdx.x & 31;
    int wid = threadIdx.x >> 5;
    if (lane == 0) {
        s_mse[wid] = mse_sum;
        s_iou[wid] = iou_sum;
        s_inc[wid] = n_inc;
        s_corr[wid] = n_corr;
    }
    __syncthreads();
    if (wid == 0) {
        mse_sum = (lane < 8) ? s_mse[lane] : 0.f;
        iou_sum = (lane < 8) ? s_iou[lane] : 0.f;
        n_inc   = (lane < 8) ? s_inc[lane] : 0u;
        n_corr  = (lane < 8) ? s_corr[lane] : 0u;
        #pragma unroll
        for (int off = 4; off > 0; off >>= 1) {
            mse_sum += __shfl_down_sync(0xffu, mse_sum, off);
            iou_sum += __shfl_down_sync(0xffu, iou_sum, off);
            n_inc   += __shfl_down_sync(0xffu, n_inc, off);
            n_corr  += __shfl_down_sync(0xffu, n_corr, off);
        }
        if (lane == 0) {
            atomicAdd(&g_mse_sum, (double)mse_sum);
            atomicAdd(&g_iou_sum, (double)iou_sum);
            atomicAdd(&g_n_inc, (unsigned long long)n_inc);
            atomicAdd(&g_n_corr, (unsigned long long)n_corr);
        }
    }
}

__global__ void finalize_kernel(float* __restrict__ out) {
    double mse_sum = g_mse_sum;
    double iou_sum = g_iou_sum;
    unsigned long long n_inc = g_n_inc;
    unsigned long long n_corr = g_n_corr;

    double denom_mse = (double)(n_inc * 4ull > 0ull ? n_inc * 4ull : 1ull);
    double mse_mean = mse_sum / denom_mse;
    double denom_iou = (double)(n_corr > 0ull ? n_corr : 1ull);
    double iou_mean = iou_sum / denom_iou;

    double res_full = iou_mean + (n_inc > 0ull ? -mse_mean : 0.0);
    double res = (n_corr > 0ull) ? res_full : -mse_mean;
    out[0] = (float)res;
}

extern "C" void kernel_launch(void* const* d_in, const int* in_sizes, int n_in,
                              void* d_out, int out_size) {
    const float4* pr = (const float4*)d_in[0];
    const float4* gt = (const float4*)d_in[1];
    int n = in_sizes[0] / 4;  // boxes

    init_kernel<<<1, 1>>>();
    int threads = 256;
    int blocks = 2048;
    iou_reduce_kernel<<<blocks, threads>>>(pr, gt, n);
    finalize_kernel<<<1, 1>>>((float*)d_out);
}